// round 3
// baseline (speedup 1.0000x reference)
#include <cuda_runtime.h>
#include <cstdint>

// LaneATT line NMS — Round 3: warp-local greedy loop, hierarchical argmax.
//
// R2 lesson: per-iteration block-wide 8192-key scans + 4 __syncthreads made the
// loop barrier-bound. The loop's working set (1 candidate + <=8 kept rows) fits
// in one warp, so:
//   Phase 1 (block): build u64 keys in shared + 32 per-chunk maxima. 1 barrier.
//   Phase 2 (warp 0): argmax = max-of-32-chunkmax -> scan 1 chunk (256 keys).
//     Clear winner, rescan that chunk only. Candidate LDGs issued before the
//     rescan to hide latency. Suppression via warp shuffles. NO barriers.
//   Phase 3 (block): write output.
// key = (orderable_score << 32) | (0xFFFFFFFF - idx): max == stable argsort(-s)
// head. Sentinel 0 = removed. Exact num_kept when pool exhausts under topk.

#define N_OFFSETS 72
#define N_STRIPS 71
#define PROP_COLS 77
#define MAX_KEPT 32
#define NT 1024
#define NWARPS 32
#define FULL 0xFFFFFFFFu

__global__ __launch_bounds__(NT, 1)
void laneatt_nms_kernel(const float* __restrict__ proposals,
                        const float* __restrict__ scores,
                        const int* __restrict__ thres_ptr,
                        const int* __restrict__ topk_ptr,
                        float* __restrict__ out,
                        int out_size, int n)
{
    extern __shared__ uint64_t keys[];              // n entries

    __shared__ uint64_t chunkmax[NWARPS];
    __shared__ float kept_xs[MAX_KEPT][N_OFFSETS];
    __shared__ int   kept_s[MAX_KEPT];
    __shared__ int   kept_e[MAX_KEPT];
    __shared__ int   kept_gi[MAX_KEPT];
    __shared__ int   sh_kc;

    const int tid  = threadIdx.x;
    const int warp = tid >> 5;
    const int lane = tid & 31;
    const int cs   = (n + NWARPS - 1) / NWARPS;     // chunk size (256 @ n=8192)

    // ---- scalar params (robust to int32 or float32 bit encoding) ----
    int tv = *thres_ptr;
    float thr = (tv >= 0 && tv < 1000000) ? (float)tv : __int_as_float(tv);
    int tk = *topk_ptr;
    if (tk <= 0 || tk > 100000) tk = (int)__int_as_float(tk);
    if (tk > MAX_KEPT) tk = MAX_KEPT;

    // ---- Phase 1: build keys + per-chunk maxima ----
    {
        int lo = warp * cs, hi = min(lo + cs, n);
        uint64_t m = 0;
        for (int idx = lo + lane; idx < hi; idx += 32) {
            uint32_t b = __float_as_uint(scores[idx]);
            b = (b & 0x80000000u) ? ~b : (b | 0x80000000u);   // orderable bits
            uint64_t k = ((uint64_t)b << 32) | (FULL - (uint32_t)idx);
            keys[idx] = k;
            if (k > m) m = k;
        }
        #pragma unroll
        for (int o = 16; o > 0; o >>= 1) {
            uint64_t v = __shfl_xor_sync(FULL, m, o);
            if (v > m) m = v;
        }
        if (lane == 0) chunkmax[warp] = m;
    }
    __syncthreads();

    // ---- Phase 2: warp-0 greedy loop (no block barriers) ----
    if (warp == 0) {
        int kc = 0;
        for (int iter = 0; iter < n && kc < tk; ++iter) {
            // level-1 argmax over 32 chunk maxima
            uint64_t cm = chunkmax[lane];
            uint64_t gm = cm;
            #pragma unroll
            for (int o = 16; o > 0; o >>= 1) {
                uint64_t v = __shfl_xor_sync(FULL, gm, o);
                if (v > gm) gm = v;
            }
            if (gm == 0) break;                      // pool exhausted
            int c = __ffs(__ballot_sync(FULL, cm == gm)) - 1;

            // level-2: scan winning chunk
            int lo = c * cs, hi = min(lo + cs, n);
            uint64_t best = 0; int bidx = -1;
            for (int idx = lo + lane; idx < hi; idx += 32) {
                uint64_t u = keys[idx];
                if (u > best) { best = u; bidx = idx; }
            }
            uint64_t bm = best;
            #pragma unroll
            for (int o = 16; o > 0; o >>= 1) {
                uint64_t v = __shfl_xor_sync(FULL, bm, o);
                if (v > bm) bm = v;
            }
            int owner = __ffs(__ballot_sync(FULL, best == bm)) - 1;
            int wi = __shfl_sync(FULL, bidx, owner);
            int gi = (int)(FULL - (uint32_t)(bm & 0xFFFFFFFFull));

            // issue candidate row loads NOW (hidden behind chunk rescan)
            const float* row = proposals + (size_t)gi * PROP_COLS;
            float hdr = (lane < 5) ? row[lane] : 0.0f;
            float cx0 = row[5 + lane];
            float cx1 = row[5 + 32 + lane];
            float cx2 = (lane < N_OFFSETS - 64) ? row[5 + 64 + lane] : 0.0f;

            // clear winner + refresh this chunk's max
            if (lane == owner) keys[wi] = 0;
            __syncwarp();
            uint64_t nb = 0;
            for (int idx = lo + lane; idx < hi; idx += 32) {
                uint64_t u = keys[idx];
                if (u > nb) nb = u;
            }
            #pragma unroll
            for (int o = 16; o > 0; o >>= 1) {
                uint64_t v = __shfl_xor_sync(FULL, nb, o);
                if (v > nb) nb = v;
            }
            if (lane == 0) chunkmax[c] = nb;

            // candidate start/end (round half-even matches jnp.round)
            float sy = __shfl_sync(FULL, hdr, 2);
            float ln = __shfl_sync(FULL, hdr, 4);
            int s = (int)rintf(sy * (float)N_STRIPS);
            int e = min(s + (int)rintf(ln) - 1, N_STRIPS);

            // suppression vs kept set (all warp-uniform branches)
            bool suppressed = false;
            for (int j = 0; j < kc; ++j) {
                int ps = max(s, kept_s[j]);
                int pe = min(e, kept_e[j]);
                float d = 0.0f;
                int o0 = lane, o1 = lane + 32, o2 = lane + 64;
                if (o0 >= ps && o0 <= pe) d += fabsf(cx0 - kept_xs[j][o0]);
                if (o1 >= ps && o1 <= pe) d += fabsf(cx1 - kept_xs[j][o1]);
                if (o2 < N_OFFSETS && o2 >= ps && o2 <= pe)
                    d += fabsf(cx2 - kept_xs[j][o2]);
                #pragma unroll
                for (int o = 16; o > 0; o >>= 1)
                    d += __shfl_xor_sync(FULL, d, o);
                float cnt = (float)max(pe - ps + 1, 1);
                if (pe >= ps && d / cnt < thr) { suppressed = true; break; }
            }

            if (!suppressed) {
                kept_xs[kc][lane]      = cx0;
                kept_xs[kc][lane + 32] = cx1;
                if (lane < N_OFFSETS - 64) kept_xs[kc][lane + 64] = cx2;
                if (lane == 0) { kept_s[kc] = s; kept_e[kc] = e; kept_gi[kc] = gi; }
                ++kc;
            }
        }
        if (lane == 0) sh_kc = kc;
    }
    __syncthreads();

    // ---- Phase 3: write output: tk rows of 78, then num_kept ----
    int kc = sh_kc;
    int row_elems = tk * (PROP_COLS + 1);
    for (int idx = tid; idx < out_size; idx += NT) {
        float v = 0.0f;
        if (idx < row_elems) {
            int r = idx / (PROP_COLS + 1);
            int c = idx - r * (PROP_COLS + 1);
            if (r < kc) {
                int gi = kept_gi[r];
                v = (c < PROP_COLS) ? proposals[(size_t)gi * PROP_COLS + c]
                                    : scores[gi];
            }
        } else if (idx == row_elems) {
            v = (float)kc;
        }
        out[idx] = v;
    }
}

extern "C" void kernel_launch(void* const* d_in, const int* in_sizes, int n_in,
                              void* d_out, int out_size) {
    const float* proposals = (const float*)d_in[0];
    const float* scores    = (const float*)d_in[1];
    const int*   thres     = (const int*)d_in[2];
    const int*   topk      = (const int*)d_in[3];
    float* out = (float*)d_out;

    int n = in_sizes[1];                          // scores element count
    size_t smem = (size_t)n * sizeof(uint64_t);

    static bool attr_set = false;                 // idempotent attribute only
    if (!attr_set) {
        cudaFuncSetAttribute(laneatt_nms_kernel,
                             cudaFuncAttributeMaxDynamicSharedMemorySize,
                             (int)smem);
        attr_set = true;
    }

    laneatt_nms_kernel<<<1, NT, smem>>>(proposals, scores, thres, topk,
                                        out, out_size, n);
}

// round 4
// speedup vs baseline: 1.8691x; 1.8691x over previous
#include <cuda_runtime.h>
#include <cstdint>

// LaneATT line NMS — Round 4: warp-local greedy loop with ALL latency chains
// removed: precomputed per-chunk sorted top-8 lists (no per-iter scans),
// REDUX-based warp max (no 5-deep shuffle trees), lane-per-kept-item
// suppression (one ballot, zero reductions), prefetched head rows (no exposed
// LDG on the critical path).
//
// key = (orderable_score << 32) | (0xFFFFFFFF - idx): u64 max == head of
// stable argsort(-scores). Sentinel 0 = empty/consumed. Exact for arbitrary
// inputs: if a chunk's top-8 is exhausted (needs 8 pops from one chunk among
// the examined candidates — pathological), we rescan that chunk from the keys
// array where consumed entries are zeroed.

#define N_OFFSETS 72
#define N_STRIPS 71
#define PROP_COLS 77
#define MAXK 16
#define NT 1024
#define NWARPS 32
#define FULL 0xFFFFFFFFu
#define ROWPAD 80

// warp-wide u64 max via REDUX halves (all lanes get result)
__device__ __forceinline__ uint64_t warp_max_u64(uint64_t v) {
    uint32_t hi = (uint32_t)(v >> 32), lo = (uint32_t)v;
    uint32_t mhi = __reduce_max_sync(FULL, hi);
    uint32_t lo2 = (hi == mhi) ? lo : 0u;
    uint32_t mlo = __reduce_max_sync(FULL, lo2);
    return ((uint64_t)mhi << 32) | mlo;
}

__global__ __launch_bounds__(NT, 1)
void laneatt_nms_kernel(const float* __restrict__ proposals,
                        const float* __restrict__ scores,
                        const int* __restrict__ thres_ptr,
                        const int* __restrict__ topk_ptr,
                        float* __restrict__ out,
                        int out_size, int n)
{
    extern __shared__ uint64_t keys[];                 // n entries

    __shared__ uint64_t top8[NWARPS][8];
    __shared__ uint64_t heads[NWARPS];
    __shared__ int      cursor_s[NWARPS];
    __shared__ int      pregi[NWARPS];
    __shared__ float    prerow[NWARPS][ROWPAD];
    __shared__ float    kept_xsT[N_OFFSETS][MAXK];     // [offset][kept]: lane-stride-1
    __shared__ float    cand_sh[ROWPAD];
    __shared__ int      kept_s[MAXK], kept_e[MAXK], kept_gi[MAXK];
    __shared__ int      sh_kc;

    const int tid  = threadIdx.x;
    const int warp = tid >> 5;
    const int lane = tid & 31;
    const int cs   = (n + NWARPS - 1) / NWARPS;        // 256 @ n=8192

    // ---- scalar params (robust to int32 or float32 bit encoding) ----
    int tv = *thres_ptr;
    float thr = (tv >= 0 && tv < 1000000) ? (float)tv : __int_as_float(tv);
    int tk = *topk_ptr;
    if (tk <= 0 || tk > 100000) tk = (int)__int_as_float(tk);
    if (tk > MAXK) tk = MAXK;

    // ================= Phase 1 (all warps in parallel) =================
    {
        const int c = warp;
        const int lo = c * cs, hi2 = min(lo + cs, n);

        // build keys; cache this lane's elements in registers when they fit
        uint64_t vals[8];
        const bool in_regs = (cs <= 8 * 32);
        #pragma unroll
        for (int t = 0; t < 8; ++t) {
            int idx = lo + lane + t * 32;
            uint64_t k = 0;
            if (idx < hi2) {
                uint32_t b = __float_as_uint(scores[idx]);
                b = (b & 0x80000000u) ? ~b : (b | 0x80000000u);
                k = ((uint64_t)b << 32) | (FULL - (uint32_t)idx);
                keys[idx] = k;
            }
            vals[t] = k;
        }
        if (!in_regs) {            // generic: finish storing remaining keys
            for (int idx = lo + lane + 8 * 32; idx < hi2; idx += 32) {
                uint32_t b = __float_as_uint(scores[idx]);
                b = (b & 0x80000000u) ? ~b : (b | 0x80000000u);
                keys[idx] = ((uint64_t)b << 32) | (FULL - (uint32_t)idx);
            }
            __syncwarp();
        }

        // sorted top-8 by descending-threshold scan (keys are all distinct)
        uint64_t prev = 0xFFFFFFFFFFFFFFFFull;
        uint64_t first = 0;
        int t = 0;
        for (; t < 8; ++t) {
            uint64_t m = 0;
            if (in_regs) {
                #pragma unroll
                for (int q = 0; q < 8; ++q) {
                    uint64_t u = vals[q];
                    if (u < prev && u > m) m = u;
                }
            } else {
                for (int idx = lo + lane; idx < hi2; idx += 32) {
                    uint64_t u = keys[idx];
                    if (u < prev && u > m) m = u;
                }
            }
            uint64_t wm = warp_max_u64(m);
            if (lane == 0) top8[c][t] = wm;
            if (t == 0) first = wm;
            if (wm == 0) break;
            prev = wm;
        }
        for (; t < 8; ++t) if (lane == 0) top8[c][t] = 0;

        int hgi = (first != 0) ? (int)(FULL - (uint32_t)first) : -1;
        if (lane == 0) { heads[c] = first; cursor_s[c] = 1; pregi[c] = hgi; }

        // prefetch the head candidate's full row
        if (hgi >= 0)
            for (int q = lane; q < PROP_COLS; q += 32)
                prerow[c][q] = proposals[(size_t)hgi * PROP_COLS + q];
    }
    __syncthreads();

    // ================= Phase 2 (warp 0 only, no block barriers) ========
    if (warp == 0) {
        int kc = 0;
        for (int guard = 0; guard < n && kc < tk; ++guard) {
            uint64_t hv = heads[lane];                 // 32 heads, LDS.64
            uint64_t gm = warp_max_u64(hv);
            if (gm == 0) break;                        // pool exhausted
            int c  = __ffs(__ballot_sync(FULL, hv == gm)) - 1;
            int gi = (int)(FULL - (uint32_t)gm);

            // candidate row: prefetched LDS fast path, LDG fallback
            const float* cand;
            if (pregi[c] == gi) {
                cand = prerow[c];
            } else {
                for (int q = lane; q < PROP_COLS; q += 32)
                    cand_sh[q] = proposals[(size_t)gi * PROP_COLS + q];
                __syncwarp();
                cand = cand_sh;
            }

            // pop: clear consumed key, advance this chunk's head
            if (lane == 0) keys[gi] = 0;
            __syncwarp();
            int cur = cursor_s[c];                      // broadcast
            uint64_t nh;
            if (cur < 8) {
                nh = top8[c][cur];
                if (lane == 0) cursor_s[c] = cur + 1;
            } else {                                    // pathological refill
                int lo = c * cs, hi2 = min(lo + cs, n);
                uint64_t m = 0;
                for (int idx = lo + lane; idx < hi2; idx += 32) {
                    uint64_t u = keys[idx];
                    if (u > m) m = u;
                }
                nh = warp_max_u64(m);
            }
            if (lane == 0) heads[c] = nh;

            // candidate interval (round half-even == jnp.round)
            float sy = cand[2], lnf = cand[4];          // broadcast LDS
            int s = (int)rintf(sy * (float)N_STRIPS);
            int e = min(s + (int)rintf(lnf) - 1, N_STRIPS);

            // suppression: lane j < kc owns kept item j; ONE ballot decides
            bool sup = false;
            if (lane < kc) {
                int ps = max(s, kept_s[lane]);
                int pe = min(e, kept_e[lane]);
                float d = 0.0f;
                #pragma unroll
                for (int k = 0; k < N_OFFSETS; ++k) {
                    if (k >= ps && k <= pe)
                        d += fabsf(cand[5 + k] - kept_xsT[k][lane]);
                }
                float cnt = (float)max(pe - ps + 1, 1);
                sup = (pe >= ps) && (d / cnt < thr);
            }
            if (__ballot_sync(FULL, sup) == 0) {        // accept
                #pragma unroll
                for (int t2 = 0; t2 < 3; ++t2) {
                    int k = lane + t2 * 32;
                    if (k < N_OFFSETS) kept_xsT[k][kc] = cand[5 + k];
                }
                if (lane == 0) { kept_s[kc] = s; kept_e[kc] = e; kept_gi[kc] = gi; }
                ++kc;
            }
            __syncwarp();   // order this iter's shared writes before next reads
        }
        if (lane == 0) sh_kc = kc;
    }
    __syncthreads();

    // ================= Phase 3: output =================
    // tk rows of 78 (77 proposal cols + score), zero-padded, then num_kept
    int kc = sh_kc;
    int row_elems = tk * (PROP_COLS + 1);
    for (int idx = tid; idx < out_size; idx += NT) {
        float v = 0.0f;
        if (idx < row_elems) {
            int r = idx / (PROP_COLS + 1);
            int c = idx - r * (PROP_COLS + 1);
            if (r < kc) {
                int gi = kept_gi[r];
                v = (c < PROP_COLS) ? proposals[(size_t)gi * PROP_COLS + c]
                                    : scores[gi];
            }
        } else if (idx == row_elems) {
            v = (float)kc;
        }
        out[idx] = v;
    }
}

extern "C" void kernel_launch(void* const* d_in, const int* in_sizes, int n_in,
                              void* d_out, int out_size) {
    const float* proposals = (const float*)d_in[0];
    const float* scores    = (const float*)d_in[1];
    const int*   thres     = (const int*)d_in[2];
    const int*   topk      = (const int*)d_in[3];
    float* out = (float*)d_out;

    int n = in_sizes[1];                          // scores element count
    size_t smem = (size_t)n * sizeof(uint64_t);

    static bool attr_set = false;                 // idempotent attribute only
    if (!attr_set) {
        cudaFuncSetAttribute(laneatt_nms_kernel,
                             cudaFuncAttributeMaxDynamicSharedMemorySize,
                             (int)smem);
        attr_set = true;
    }

    laneatt_nms_kernel<<<1, NT, smem>>>(proposals, scores, thres, topk,
                                        out, out_size, n);
}

// round 5
// speedup vs baseline: 2.0825x; 1.1142x over previous
#include <cuda_runtime.h>
#include <cstdint>

// LaneATT line NMS — Round 5: R4 structure (per-chunk top lists + warp-local
// greedy) with the two remaining hot spots cut:
//   * suppression test: float4 LDS (36 loads/lane vs 144), exact k-ascending
//     accumulation order preserved (bit-identical decisions vs reference)
//   * phase 1: top-4 per chunk (half the serial REDUX-scan chain); exact
//     rescan fallback via zeroed keys[] if a chunk is popped >4 times
// Rows are stored left-shifted by 3 floats in shared so the 72 xs values
// start 16B-aligned; kept xs use stride 76 (conflict-free mod 32).

#define N_OFFSETS 72
#define N_STRIPS 71
#define PROP_COLS 77
#define MAXK 16
#define NT 1024
#define NWARPS 32
#define FULL 0xFFFFFFFFu
#define TOPT 4            // per-chunk precomputed list length
#define RSH 3             // row shift: col q lives at [RSH+q], xs at [8..79]
#define KSTRIDE 76        // kept-row stride in floats (16B aligned, no conflicts)

// warp-wide u64 max via REDUX halves (all lanes get result)
__device__ __forceinline__ uint64_t warp_max_u64(uint64_t v) {
    uint32_t hi = (uint32_t)(v >> 32), lo = (uint32_t)v;
    uint32_t mhi = __reduce_max_sync(FULL, hi);
    uint32_t lo2 = (hi == mhi) ? lo : 0u;
    uint32_t mlo = __reduce_max_sync(FULL, lo2);
    return ((uint64_t)mhi << 32) | mlo;
}

__global__ __launch_bounds__(NT, 1)
void laneatt_nms_kernel(const float* __restrict__ proposals,
                        const float* __restrict__ scores,
                        const int* __restrict__ thres_ptr,
                        const int* __restrict__ topk_ptr,
                        float* __restrict__ out,
                        int out_size, int n)
{
    extern __shared__ uint64_t keys[];                  // n entries

    __shared__ uint64_t toplist[NWARPS][TOPT];
    __shared__ uint64_t heads[NWARPS];
    __shared__ int      cursor_s[NWARPS];
    __shared__ int      pregi[NWARPS];
    __shared__ __align__(16) float prerow[NWARPS][80];  // shifted rows
    __shared__ __align__(16) float kept_xs[MAXK][KSTRIDE];
    __shared__ __align__(16) float cand_sh[80];
    __shared__ int      kept_s[MAXK], kept_e[MAXK], kept_gi[MAXK];
    __shared__ int      sh_kc;

    const int tid  = threadIdx.x;
    const int warp = tid >> 5;
    const int lane = tid & 31;
    const int cs   = (n + NWARPS - 1) / NWARPS;         // 256 @ n=8192

    // ---- scalar params (robust to int32 or float32 bit encoding) ----
    int tv = *thres_ptr;
    float thr = (tv >= 0 && tv < 1000000) ? (float)tv : __int_as_float(tv);
    int tk = *topk_ptr;
    if (tk <= 0 || tk > 100000) tk = (int)__int_as_float(tk);
    if (tk > MAXK) tk = MAXK;

    // ================= Phase 1 (all warps in parallel) =================
    {
        const int c = warp;
        const int lo = c * cs, hi2 = min(lo + cs, n);

        // build keys; cache this lane's elements in registers when they fit
        uint64_t vals[8];
        const bool in_regs = (cs <= 8 * 32);
        #pragma unroll
        for (int t = 0; t < 8; ++t) {
            int idx = lo + lane + t * 32;
            uint64_t k = 0;
            if (idx < hi2) {
                uint32_t b = __float_as_uint(scores[idx]);
                b = (b & 0x80000000u) ? ~b : (b | 0x80000000u);
                k = ((uint64_t)b << 32) | (FULL - (uint32_t)idx);
                keys[idx] = k;
            }
            vals[t] = k;
        }
        if (!in_regs) {
            for (int idx = lo + lane + 8 * 32; idx < hi2; idx += 32) {
                uint32_t b = __float_as_uint(scores[idx]);
                b = (b & 0x80000000u) ? ~b : (b | 0x80000000u);
                keys[idx] = ((uint64_t)b << 32) | (FULL - (uint32_t)idx);
            }
            __syncwarp();
        }

        // sorted top-TOPT via descending-threshold scans (keys distinct)
        uint64_t prev = 0xFFFFFFFFFFFFFFFFull;
        uint64_t first = 0;
        int t = 0;
        for (; t < TOPT; ++t) {
            uint64_t m = 0;
            if (in_regs) {
                #pragma unroll
                for (int q = 0; q < 8; ++q) {
                    uint64_t u = vals[q];
                    if (u < prev && u > m) m = u;
                }
            } else {
                for (int idx = lo + lane; idx < hi2; idx += 32) {
                    uint64_t u = keys[idx];
                    if (u < prev && u > m) m = u;
                }
            }
            uint64_t wm = warp_max_u64(m);
            if (lane == 0) toplist[c][t] = wm;
            if (t == 0) first = wm;
            if (wm == 0) break;
            prev = wm;
        }
        for (; t < TOPT; ++t) if (lane == 0) toplist[c][t] = 0;

        int hgi = (first != 0) ? (int)(FULL - (uint32_t)first) : -1;
        if (lane == 0) { heads[c] = first; cursor_s[c] = 1; pregi[c] = hgi; }

        // prefetch the head candidate's row (shifted by RSH)
        if (hgi >= 0) {
            const float* row = proposals + (size_t)hgi * PROP_COLS;
            for (int q = lane; q < PROP_COLS; q += 32)
                prerow[c][RSH + q] = row[q];
        }
    }
    __syncthreads();

    // ================= Phase 2 (warp 0 only, no block barriers) ========
    if (warp == 0) {
        int kc = 0;
        for (int guard = 0; guard < n && kc < tk; ++guard) {
            uint64_t hv = heads[lane];
            uint64_t gm = warp_max_u64(hv);
            if (gm == 0) break;                         // pool exhausted
            int c  = __ffs(__ballot_sync(FULL, hv == gm)) - 1;
            int gi = (int)(FULL - (uint32_t)gm);

            // candidate row (shifted layout): prefetched or LDG fallback
            const float* cand;
            if (pregi[c] == gi) {
                cand = prerow[c];
            } else {
                const float* row = proposals + (size_t)gi * PROP_COLS;
                for (int q = lane; q < PROP_COLS; q += 32)
                    cand_sh[RSH + q] = row[q];
                __syncwarp();
                cand = cand_sh;
            }

            // pop: clear consumed key, advance chunk head
            if (lane == 0) keys[gi] = 0;
            __syncwarp();
            int cur = cursor_s[c];
            uint64_t nh;
            if (cur < TOPT) {
                nh = toplist[c][cur];
                if (lane == 0) cursor_s[c] = cur + 1;
            } else {                                    // pathological refill
                int lo = c * cs, hi2 = min(lo + cs, n);
                uint64_t m = 0;
                for (int idx = lo + lane; idx < hi2; idx += 32) {
                    uint64_t u = keys[idx];
                    if (u > m) m = u;
                }
                nh = warp_max_u64(m);
            }
            if (lane == 0) heads[c] = nh;

            // candidate interval (round half-even == jnp.round)
            float sy = cand[RSH + 2], lnf = cand[RSH + 4];
            int s = (int)rintf(sy * (float)N_STRIPS);
            int e = min(s + (int)rintf(lnf) - 1, N_STRIPS);

            // suppression: lane j < kc owns kept item j; float4 loads,
            // accumulation in exact ascending-k order (matches reference)
            bool sup = false;
            if (lane < kc) {
                int ps = max(s, kept_s[lane]);
                int pe = min(e, kept_e[lane]);
                float d = 0.0f;
                const float4* c4 = (const float4*)(cand + 8);
                const float4* k4 = (const float4*)(kept_xs[lane]);
                #pragma unroll
                for (int g = 0; g < N_OFFSETS / 4; ++g) {
                    float4 a = c4[g];
                    float4 b = k4[g];
                    int k0 = 4 * g;
                    if (k0     >= ps && k0     <= pe) d += fabsf(a.x - b.x);
                    if (k0 + 1 >= ps && k0 + 1 <= pe) d += fabsf(a.y - b.y);
                    if (k0 + 2 >= ps && k0 + 2 <= pe) d += fabsf(a.z - b.z);
                    if (k0 + 3 >= ps && k0 + 3 <= pe) d += fabsf(a.w - b.w);
                }
                float cnt = (float)max(pe - ps + 1, 1);
                sup = (pe >= ps) && (d / cnt < thr);
            }
            if (__ballot_sync(FULL, sup) == 0) {        // accept
                #pragma unroll
                for (int t2 = 0; t2 < 3; ++t2) {
                    int k = lane + t2 * 32;
                    if (k < N_OFFSETS) kept_xs[kc][k] = cand[8 + k];
                }
                if (lane == 0) { kept_s[kc] = s; kept_e[kc] = e; kept_gi[kc] = gi; }
                ++kc;
            }
            __syncwarp();   // order this iter's shared writes before next reads
        }
        if (lane == 0) sh_kc = kc;
    }
    __syncthreads();

    // ================= Phase 3: output =================
    // tk rows of 78 (77 proposal cols + score), zero-padded, then num_kept
    int kc = sh_kc;
    int row_elems = tk * (PROP_COLS + 1);
    for (int idx = tid; idx < out_size; idx += NT) {
        float v = 0.0f;
        if (idx < row_elems) {
            int r = idx / (PROP_COLS + 1);
            int c = idx - r * (PROP_COLS + 1);
            if (r < kc) {
                int gi = kept_gi[r];
                v = (c < PROP_COLS) ? proposals[(size_t)gi * PROP_COLS + c]
                                    : scores[gi];
            }
        } else if (idx == row_elems) {
            v = (float)kc;
        }
        out[idx] = v;
    }
}

extern "C" void kernel_launch(void* const* d_in, const int* in_sizes, int n_in,
                              void* d_out, int out_size) {
    const float* proposals = (const float*)d_in[0];
    const float* scores    = (const float*)d_in[1];
    const int*   thres     = (const int*)d_in[2];
    const int*   topk      = (const int*)d_in[3];
    float* out = (float*)d_out;

    int n = in_sizes[1];                          // scores element count
    size_t smem = (size_t)n * sizeof(uint64_t);

    static bool attr_set = false;                 // idempotent attribute only
    if (!attr_set) {
        cudaFuncSetAttribute(laneatt_nms_kernel,
                             cudaFuncAttributeMaxDynamicSharedMemorySize,
                             (int)smem);
        attr_set = true;
    }

    laneatt_nms_kernel<<<1, NT, smem>>>(proposals, scores, thres, topk,
                                        out, out_size, n);
}

// round 6
// speedup vs baseline: 2.3176x; 1.1129x over previous
#include <cuda_runtime.h>
#include <cstdint>

// LaneATT line NMS — Round 6: fully parallel fast path.
// The examined-candidate order is independent of suppression outcomes, so the
// first M=16 examined candidates are exactly the global top-16 scores:
//   P1  (32 warps): keys + per-chunk sorted top-4 (REDUX threshold scans)
//   P2a (128 thr):  rank-count merge of 32x4 keys -> sorted global L[0..15]
//   P2b (16 warps): load candidate rows + s/e in parallel
//   P2c (32 warps): symmetric 16x16 suppression matrix, 120 pairs in parallel
//   P2d (1 thread): trivial greedy bitmask walk (~40 instructions)
// Exactness guards (chunk top-4 exhausted mid-walk, or 16 candidates
// insufficient) drop to a proven block-cooperative fallback loop over keys[].

#define N_OFFSETS 72
#define N_STRIPS 71
#define PROP_COLS 77
#define MAXK 16
#define M 16
#define NT 1024
#define NWARPS 32
#define TOPT 4
#define FULL 0xFFFFFFFFu

// warp-wide u64 max via REDUX halves (all lanes get result)
__device__ __forceinline__ uint64_t warp_max_u64(uint64_t v) {
    uint32_t hi = (uint32_t)(v >> 32), lo = (uint32_t)v;
    uint32_t mhi = __reduce_max_sync(FULL, hi);
    uint32_t lo2 = (hi == mhi) ? lo : 0u;
    uint32_t mlo = __reduce_max_sync(FULL, lo2);
    return ((uint64_t)mhi << 32) | mlo;
}

__global__ __launch_bounds__(NT, 1)
void laneatt_nms_kernel(const float* __restrict__ proposals,
                        const float* __restrict__ scores,
                        const int* __restrict__ thres_ptr,
                        const int* __restrict__ topk_ptr,
                        float* __restrict__ out,
                        int out_size, int n)
{
    extern __shared__ uint64_t keys[];                 // n entries

    __shared__ uint64_t toplist[NWARPS * TOPT];        // flat 128 keys
    __shared__ uint64_t L[M];                          // sorted global top-M
    __shared__ int      Lgi[M], Lcs[M], Lce[M];
    __shared__ __align__(16) float cxs[M][80];         // candidate xs rows
    __shared__ uint32_t Smask[M];                      // suppression bitmasks
    __shared__ int      kept_gi[MAXK], kept_slot[MAXK];
    __shared__ int      sh_kc, sh_consumed, sh_fb;
    // fallback-only state
    __shared__ float    kept_xs[MAXK][N_OFFSETS];
    __shared__ int      kept_s[MAXK], kept_e[MAXK];
    __shared__ uint64_t wmax_sh[NWARPS];
    __shared__ uint64_t sh_win;
    __shared__ float    cand2[N_OFFSETS];
    __shared__ int      sh_cs2, sh_ce2, supp[MAXK], sh_accept;

    const int tid  = threadIdx.x;
    const int warp = tid >> 5;
    const int lane = tid & 31;
    const int cs   = (n + NWARPS - 1) / NWARPS;

    // ---- scalar params (robust to int32 or float32 bit encoding) ----
    int tv = *thres_ptr;
    float thr = (tv >= 0 && tv < 1000000) ? (float)tv : __int_as_float(tv);
    int tk = *topk_ptr;
    if (tk <= 0 || tk > 100000) tk = (int)__int_as_float(tk);
    if (tk > MAXK) tk = MAXK;

    if (tid < M) { L[tid] = 0; Smask[tid] = 0; }

    // ================= P1: keys + per-chunk sorted top-4 ===============
    {
        const int c = warp;
        const int lo = c * cs, hi2 = min(lo + cs, n);
        uint64_t vals[8];
        const bool in_regs = (cs <= 8 * 32);
        #pragma unroll
        for (int t = 0; t < 8; ++t) {
            int idx = lo + lane + t * 32;
            uint64_t k = 0;
            if (idx < hi2) {
                uint32_t b = __float_as_uint(scores[idx]);
                b = (b & 0x80000000u) ? ~b : (b | 0x80000000u);
                k = ((uint64_t)b << 32) | (FULL - (uint32_t)idx);
                keys[idx] = k;
            }
            vals[t] = k;
        }
        if (!in_regs) {
            for (int idx = lo + lane + 8 * 32; idx < hi2; idx += 32) {
                uint32_t b = __float_as_uint(scores[idx]);
                b = (b & 0x80000000u) ? ~b : (b | 0x80000000u);
                keys[idx] = ((uint64_t)b << 32) | (FULL - (uint32_t)idx);
            }
            __syncwarp();
        }
        uint64_t prev = 0xFFFFFFFFFFFFFFFFull;
        int t = 0;
        for (; t < TOPT; ++t) {
            uint64_t m = 0;
            if (in_regs) {
                #pragma unroll
                for (int q = 0; q < 8; ++q) {
                    uint64_t u = vals[q];
                    if (u < prev && u > m) m = u;
                }
            } else {
                for (int idx = lo + lane; idx < hi2; idx += 32) {
                    uint64_t u = keys[idx];
                    if (u < prev && u > m) m = u;
                }
            }
            uint64_t wm = warp_max_u64(m);
            if (lane == 0) toplist[c * TOPT + t] = wm;
            if (wm == 0) break;
            prev = wm;
        }
        for (; t < TOPT; ++t) if (lane == 0) toplist[c * TOPT + t] = 0;
    }
    __syncthreads();

    // ================= P2a: rank-count merge -> sorted L ===============
    if (tid < NWARPS * TOPT) {
        uint64_t key = toplist[tid];
        if (key) {
            int r = 0;
            #pragma unroll 4
            for (int q = 0; q < NWARPS * TOPT; ++q) r += (toplist[q] > key);
            if (r < M) L[r] = key;
        }
    }
    __syncthreads();

    // ================= P2b: parallel candidate prep ====================
    if (warp < M) {
        uint64_t k = L[warp];
        int gi = k ? (int)(FULL - (uint32_t)k) : -1;
        if (lane == 0) Lgi[warp] = gi;
        if (gi >= 0) {
            const float* row = proposals + (size_t)gi * PROP_COLS;
            #pragma unroll
            for (int t = 0; t < 3; ++t) {
                int q = lane + t * 32;
                if (q < N_OFFSETS) cxs[warp][q] = row[5 + q];
            }
            if (lane == 0) {
                int s = (int)rintf(row[2] * (float)N_STRIPS);   // half-even
                int e = min(s + (int)rintf(row[4]) - 1, N_STRIPS);
                Lcs[warp] = s; Lce[warp] = e;
            }
        }
    }
    __syncthreads();

    // ================= P2c: symmetric suppression matrix ===============
    #pragma unroll
    for (int r = 0; r < 4; ++r) {
        int p = warp + r * NWARPS;
        if (p < M * (M - 1) / 2) {
            int i = 0, pp = p;
            while (pp >= M - 1 - i) { pp -= (M - 1 - i); ++i; }
            int j = i + 1 + pp;
            if (Lgi[i] >= 0 && Lgi[j] >= 0) {
                int ps = max(Lcs[i], Lcs[j]);
                int pe = min(Lce[i], Lce[j]);
                float d = 0.0f;
                #pragma unroll
                for (int t = 0; t < 3; ++t) {
                    int k = lane + t * 32;
                    if (k < N_OFFSETS && k >= ps && k <= pe)
                        d += fabsf(cxs[i][k] - cxs[j][k]);
                }
                #pragma unroll
                for (int o = 16; o > 0; o >>= 1)
                    d += __shfl_xor_sync(FULL, d, o);
                if (lane == 0) {
                    float cnt = (float)max(pe - ps + 1, 1);
                    if ((pe >= ps) && (d / cnt < thr)) {
                        atomicOr(&Smask[i], 1u << j);
                        atomicOr(&Smask[j], 1u << i);
                    }
                }
            }
        }
    }
    __syncthreads();

    // ================= P2d: scalar greedy walk =========================
    if (tid == 0) {
        uint32_t removed = 0;
        int cnt[NWARPS];
        #pragma unroll
        for (int c = 0; c < NWARPS; ++c) cnt[c] = 0;
        int kc = 0, consumed = 0, fb = 0;
        bool exh = false;
        for (int i = 0; i < M; ++i) {
            if (kc >= tk) break;
            int gi = Lgi[i];
            if (gi < 0) break;                   // pool exhausted (exact)
            if (exh) { fb = 1; break; }          // chunk top-4 used up: order
                                                 // beyond here unknown
            if (++cnt[gi / cs] == TOPT) exh = true;
            consumed = i + 1;
            if (!((removed >> i) & 1u)) {
                kept_gi[kc] = gi; kept_slot[kc] = i; ++kc;
                removed |= Smask[i];
            }
        }
        if (kc < tk) fb = 1;   // continue exactly (no-op if pool truly empty)
        sh_kc = kc; sh_consumed = consumed; sh_fb = fb;
    }
    __syncthreads();

    // ================= Fallback (cold, exact) ==========================
    if (sh_fb) {
        // zero consumed keys; seed kept arrays from fast-path accepts
        for (int t = tid; t < sh_consumed; t += NT) keys[Lgi[t]] = 0;
        for (int j = warp; j < sh_kc; j += NWARPS) {
            int sl = kept_slot[j];
            #pragma unroll
            for (int t = 0; t < 3; ++t) {
                int q = lane + t * 32;
                if (q < N_OFFSETS) kept_xs[j][q] = cxs[sl][q];
            }
            if (lane == 0) { kept_s[j] = Lcs[sl]; kept_e[j] = Lce[sl]; }
        }
        __syncthreads();

        int kc = sh_kc;
        for (int it = 0; it < n && kc < tk; ++it) {
            uint64_t m = 0;
            for (int i = tid; i < n; i += NT) {
                uint64_t v = keys[i];
                if (v > m) m = v;
            }
            m = warp_max_u64(m);
            if (lane == 0) wmax_sh[warp] = m;
            __syncthreads();
            if (warp == 0) {
                uint64_t v = wmax_sh[lane];
                v = warp_max_u64(v);
                if (lane == 0) sh_win = v;
            }
            __syncthreads();
            uint64_t win = sh_win;
            if (win == 0) break;
            int gi = (int)(FULL - (uint32_t)win);
            const float* row = proposals + (size_t)gi * PROP_COLS;
            if (tid < N_OFFSETS) cand2[tid] = row[5 + tid];
            if (tid == 0) {
                keys[gi] = 0;
                int s = (int)rintf(row[2] * (float)N_STRIPS);
                int e = min(s + (int)rintf(row[4]) - 1, N_STRIPS);
                sh_cs2 = s; sh_ce2 = e;
            }
            __syncthreads();
            if (warp < kc) {
                int ps = max(sh_cs2, kept_s[warp]);
                int pe = min(sh_ce2, kept_e[warp]);
                float d = 0.0f;
                #pragma unroll
                for (int t = 0; t < 3; ++t) {
                    int off = lane + t * 32;
                    if (off < N_OFFSETS && off >= ps && off <= pe)
                        d += fabsf(cand2[off] - kept_xs[warp][off]);
                }
                #pragma unroll
                for (int o = 16; o > 0; o >>= 1)
                    d += __shfl_xor_sync(FULL, d, o);
                if (lane == 0) {
                    float cnt2 = (float)max(pe - ps + 1, 1);
                    supp[warp] = (pe >= ps) && (d / cnt2 < thr);
                }
            }
            __syncthreads();
            if (tid == 0) {
                int s = 0;
                for (int j = 0; j < kc; ++j) s |= supp[j];
                sh_accept = !s;
            }
            __syncthreads();
            if (sh_accept) {                       // uniform
                if (tid < N_OFFSETS) kept_xs[kc][tid] = cand2[tid];
                if (tid == 0) { kept_s[kc] = sh_cs2; kept_e[kc] = sh_ce2;
                                kept_gi[kc] = gi; }
                __syncthreads();
                ++kc;
            }
        }
        if (tid == 0) sh_kc = kc;
        __syncthreads();
    }

    // ================= Output ==========================================
    // tk rows of 78 (77 proposal cols + score), zero-padded, then num_kept
    int kc = sh_kc;
    int row_elems = tk * (PROP_COLS + 1);
    for (int idx = tid; idx < out_size; idx += NT) {
        float v = 0.0f;
        if (idx < row_elems) {
            int r = idx / (PROP_COLS + 1);
            int c = idx - r * (PROP_COLS + 1);
            if (r < kc) {
                int gi = kept_gi[r];
                v = (c < PROP_COLS) ? proposals[(size_t)gi * PROP_COLS + c]
                                    : scores[gi];
            }
        } else if (idx == row_elems) {
            v = (float)kc;
        }
        out[idx] = v;
    }
}

extern "C" void kernel_launch(void* const* d_in, const int* in_sizes, int n_in,
                              void* d_out, int out_size) {
    const float* proposals = (const float*)d_in[0];
    const float* scores    = (const float*)d_in[1];
    const int*   thres     = (const int*)d_in[2];
    const int*   topk      = (const int*)d_in[3];
    float* out = (float*)d_out;

    int n = in_sizes[1];                          // scores element count
    size_t smem = (size_t)n * sizeof(uint64_t);

    static bool attr_set = false;                 // idempotent attribute only
    if (!attr_set) {
        cudaFuncSetAttribute(laneatt_nms_kernel,
                             cudaFuncAttributeMaxDynamicSharedMemorySize,
                             (int)smem);
        attr_set = true;
    }

    laneatt_nms_kernel<<<1, NT, smem>>>(proposals, scores, thres, topk,
                                        out, out_size, n);
}